// round 9
// baseline (speedup 1.0000x reference)
#include <cuda_runtime.h>

#define ITEMS_PER_BLOCK 63          // 3 batch groups of 21 -> fused deterministic ldj sum
#define SM_STRIDE 260               // 256 cond floats + 4 pad: (4*li + 3q) mod 32 all-distinct -> conflict-free
#define SM_LDJ   (ITEMS_PER_BLOCK * SM_STRIDE)   // ldj scratch after cond area

// Robust permute parse: int32 view if it's a valid permutation of {0,1,2}, else int64.
__device__ __forceinline__ void get_perm(const void* pptr, int& p0, int& p1, int& p2)
{
    const int* pi = (const int*)pptr;
    int a = pi[0], b = pi[1], c = pi[2];
    bool ok = ((unsigned)a < 3u) && ((unsigned)b < 3u) && ((unsigned)c < 3u) &&
              (((1 << a) | (1 << b) | (1 << c)) == 7);
    if (!ok) {
        const long long* pl = (const long long*)pptr;
        a = (int)pl[0]; b = (int)pl[1]; c = (int)pl[2];
    }
    p0 = a; p1 = b; p2 = c;
}

// atan(t) for t >= 0, cephes-style two-stage range reduction, max err ~2e-7 rad.
__device__ __forceinline__ float atan_pos(float t)
{
    float y0, x;
    if (t > 2.414213562373095f)       { y0 = 1.5707963267948966f; x = __fdividef(-1.0f, t); }
    else if (t > 0.4142135623730950f) { y0 = 0.7853981633974483f; x = __fdividef(t - 1.0f, t + 1.0f); }
    else                              { y0 = 0.0f;                x = t; }
    float z = x * x;
    float p = ((8.05374449538e-2f * z - 1.38776856032e-1f) * z + 1.99777106478e-1f) * z
              - 3.33329491539e-1f;
    return y0 + fmaf(p * z, x, x);
}

// angle(hv, hr) in [0, 2*pi)
__device__ __forceinline__ float angle02pi(float hv, float hr)
{
    float ax = fabsf(hr), ay = fabsf(hv);
    float r = atan_pos(__fdividef(ay, ax));
    if (hr < 0.0f) r = 3.14159265358979323846f - r;
    if (hv < 0.0f) r = 6.28318530717958647692f - r;
    return r;
}

__global__ void __launch_bounds__(256)
mobius_kernel(const float* __restrict__ rot,
              const float* __restrict__ cond,
              const void* __restrict__ perm,
              float* __restrict__ out_rot,
              float* __restrict__ out_ldj,   // out + BN*9
              int BN)
{
    extern __shared__ float sm[];
    const int tid = threadIdx.x;
    const int block_item0 = blockIdx.x * ITEMS_PER_BLOCK;

    // ---- Phase 0: stage up to 63 items x 1KB of conditions into smem (coalesced float4) ----
    {
        const float4* src = (const float4*)(cond + (size_t)block_item0 * 256);
        #pragma unroll
        for (int it = 0; it < 16; ++it) {
            int gi = it * 256 + tid;              // float4 index within block chunk
            if (gi < ITEMS_PER_BLOCK * 64) {
                int li = gi >> 6;
                int f  = gi & 63;
                if (block_item0 + li < BN) {
                    float4 vdat = src[gi];
                    *(float4*)&sm[li * SM_STRIDE + 4 * f] = vdat;
                }
            }
        }
    }
    __syncthreads();

    const int li   = tid >> 2;                // local item 0..63 (63 inactive)
    const int q    = tid & 3;                 // lane within 4-lane group
    const int item = block_item0 + li;
    const bool active = (li < ITEMS_PER_BLOCK) && (item < BN);

    if (active) {
        int p0, p1, p2;
        get_perm(perm, p0, p1, p2);

        const float* R = rot + (size_t)item * 9;
        float x0 = R[0 * 3 + p0], x1 = R[1 * 3 + p0], x2 = R[2 * 3 + p0];
        float y0 = R[0 * 3 + p1], y1 = R[1 * 3 + p1], y2 = R[2 * 3 + p1];

        float xx = x0 * x0 + x1 * x1 + x2 * x2;
        float invxn = rsqrtf(xx);
        float r0 = -x0 * invxn, r1 = -x1 * invxn, r2 = -x2 * invxn;

        float v0 = y1 * r2 - y2 * r1;
        float v1 = y2 * r0 - y0 * r2;
        float v2 = y0 * r1 - y1 * r0;
        float invvn = rsqrtf(v0 * v0 + v1 * v1 + v2 * v2);
        v0 *= invvn; v1 *= invvn; v2 *= invvn;

        float yy = y0 * y0 + y1 * y1 + y2 * y2;
        float xy = x0 * y0 + x1 * y1 + x2 * y2;
        float xv = x0 * v0 + x1 * v1 + x2 * v2;
        float xr = x0 * r0 + x1 * r1 + x2 * r2;
        float yr = y0 * r0 + y1 * r1 + y2 * r2;
        float yv = y0 * v0 + y1 * v1 + y2 * v2;

        const float* S = sm + li * SM_STRIDE;

        float accA = 0.0f, accD = 0.0f, accS = 0.0f;

        #pragma unroll 4
        for (int j = 0; j < 16; ++j) {
            int k = j * 4 + q;
            float wt  = S[k];
            float w0  = S[64 + 3 * k];
            float w1  = S[65 + 3 * k];
            float w2c = S[66 + 3 * k];

            float a  = y0 * w0 + y1 * w1 + y2 * w2c;
            float ww = w0 * w0 + w1 * w1 + w2c * w2c;
            float xw = x0 * w0 + x1 * w1 + x2 * w2c;
            float vw = v0 * w0 + v1 * w1 + v2 * w2c;
            float rw = r0 * w0 + r1 * w1 + r2 * w2c;

            float wpn2 = ww - a * a * (2.0f - yy);     // ||w - a*y||^2
            wpn2 = fmaxf(wpn2, 1e-30f);
            float iq  = rsqrtf(wpn2);
            float sq  = wpn2 * iq;                     // sqrt
            float s   = __fdividef(0.7f, 1.0f + sq);
            float w2n = s * s * wpn2;

            float sxw = s * (xw - a * xy);
            float svw = s * (vw - a * yv);
            float srw = s * (rw - a * yr);

            float n2 = xx - 2.0f * sxw + w2n;
            float factor = __fdividef(1.0f - w2n, n2);

            float hv = factor * (xv - svw) - svw;
            float hr = factor * (xr - srw) - srw;
            float ang = angle02pi(hv, hr);

            float sp = fmaxf(wt, 0.0f) + __logf(1.0f + __expf(-fabsf(wt)));

            accA = fmaf(sp, ang, accA);
            accD = fmaf(sp, factor, accD);
            accS += sp;
        }

        // ---- 4-lane butterfly reduction (quad-local mask; quads uniformly active) ----
        const unsigned qmask = 0xFu << (threadIdx.x & 28);
        #pragma unroll
        for (int off = 1; off < 4; off <<= 1) {
            accA += __shfl_xor_sync(qmask, accA, off);
            accD += __shfl_xor_sync(qmask, accD, off);
            accS += __shfl_xor_sync(qmask, accS, off);
        }

        float invS = __fdividef(1.0f, accS);
        float ang = accA * invS;
        float dtx = accD * invS;

        float sa, ca;
        __sincosf(ang, &sa, &ca);
        float t0 = r0 * ca + v0 * sa;
        float t1 = r1 * ca + v1 * sa;
        float t2 = r2 * ca + v2 * sa;

        int d = p1 - p0;
        float z0, z1, z2;
        if (d == 1 || d == -2) {           // tz = cross(tx, y)
            z0 = t1 * y2 - t2 * y1;
            z1 = t2 * y0 - t0 * y2;
            z2 = t0 * y1 - t1 * y0;
        } else {                           // tz = cross(y, tx)
            z0 = y1 * t2 - y2 * t1;
            z1 = y2 * t0 - y0 * t2;
            z2 = y0 * t1 - y1 * t0;
        }
        float invzn = rsqrtf(z0 * z0 + z1 * z1 + z2 * z2);
        z0 *= invzn; z1 *= invzn; z2 *= invzn;

        if (q == 0) sm[SM_LDJ + li] = __logf(dtx);

        #pragma unroll
        for (int idx = q; idx < 9; idx += 4) {
            int i = idx / 3, jj = idx % 3;
            float ti = (i == 0) ? t0 : ((i == 1) ? t1 : t2);
            float yi = (i == 0) ? y0 : ((i == 1) ? y1 : y2);
            float zi = (i == 0) ? z0 : ((i == 1) ? z1 : z2);
            float val = (jj == p0) ? ti : ((jj == p1) ? yi : zi);
            out_rot[(size_t)item * 9 + idx] = val;
        }
    }

    // ---- Fused deterministic ldj sum: block owns 3 whole b-groups of 21 ----
    __syncthreads();
    if (tid < 3) {
        int first_item = tid * 21;
        if (block_item0 + first_item < BN) {
            float sum = 0.0f;
            #pragma unroll
            for (int n = 0; n < 21; ++n)
                sum += sm[SM_LDJ + first_item + n];
            out_ldj[blockIdx.x * 3 + tid] = sum;
        }
    }
}

extern "C" void kernel_launch(void* const* d_in, const int* in_sizes, int n_in,
                              void* d_out, int out_size)
{
    const float* rot = (const float*)d_in[0];
    const float* cond = (const float*)d_in[1];
    const void* perm = d_in[2];
    float* out = (float*)d_out;

    int BN = in_sizes[0] / 9;            // 86016

    const int smem_bytes = (SM_LDJ + ITEMS_PER_BLOCK) * sizeof(float);   // ~65.8 KB
    cudaFuncSetAttribute(mobius_kernel, cudaFuncAttributeMaxDynamicSharedMemorySize, smem_bytes);

    int blocks = (BN + ITEMS_PER_BLOCK - 1) / ITEMS_PER_BLOCK;           // 1366
    mobius_kernel<<<blocks, 256, smem_bytes>>>(rot, cond, perm, out, out + in_sizes[0], BN);
}

// round 12
// speedup vs baseline: 1.0045x; 1.0045x over previous
#include <cuda_runtime.h>

#define ITEMS_PER_BLOCK 63     // 3 batch groups of 21 -> fused deterministic ldj sum
#define SM_STRIDE 132          // 128 floats per item-half + 4 pad (132 % 32 == 4 -> conflict-free)
#define SM_LDJ   (ITEMS_PER_BLOCK * SM_STRIDE)   // ldj scratch after cond area

// Robust permute parse: int32 view if it's a valid permutation of {0,1,2}, else int64.
__device__ __forceinline__ void get_perm(const void* pptr, int& p0, int& p1, int& p2)
{
    const int* pi = (const int*)pptr;
    int a = pi[0], b = pi[1], c = pi[2];
    bool ok = ((unsigned)a < 3u) && ((unsigned)b < 3u) && ((unsigned)c < 3u) &&
              (((1 << a) | (1 << b) | (1 << c)) == 7);
    if (!ok) {
        const long long* pl = (const long long*)pptr;
        a = (int)pl[0]; b = (int)pl[1]; c = (int)pl[2];
    }
    p0 = a; p1 = b; p2 = c;
}

// atan(t) for t >= 0, cephes-style two-stage range reduction, max err ~2e-7 rad.
__device__ __forceinline__ float atan_pos(float t)
{
    float y0, x;
    if (t > 2.414213562373095f)       { y0 = 1.5707963267948966f; x = __fdividef(-1.0f, t); }
    else if (t > 0.4142135623730950f) { y0 = 0.7853981633974483f; x = __fdividef(t - 1.0f, t + 1.0f); }
    else                              { y0 = 0.0f;                x = t; }
    float z = x * x;
    float p = ((8.05374449538e-2f * z - 1.38776856032e-1f) * z + 1.99777106478e-1f) * z
              - 3.33329491539e-1f;
    return y0 + fmaf(p * z, x, x);
}

// angle(hv, hr) in [0, 2*pi)
__device__ __forceinline__ float angle02pi(float hv, float hr)
{
    float ax = fabsf(hr), ay = fabsf(hv);
    float r = atan_pos(__fdividef(ay, ax));
    if (hr < 0.0f) r = 3.14159265358979323846f - r;
    if (hv < 0.0f) r = 6.28318530717958647692f - r;
    return r;
}

__global__ void __launch_bounds__(256)
mobius_kernel(const float* __restrict__ rot,
              const float* __restrict__ cond,
              const void* __restrict__ perm,
              float* __restrict__ out_rot,
              float* __restrict__ out_ldj,   // out + BN*9
              int BN)
{
    extern __shared__ float sm[];
    const int tid = threadIdx.x;
    const int block_item0 = blockIdx.x * ITEMS_PER_BLOCK;

    const int li   = tid >> 2;                // local item 0..63 (63 inactive)
    const int q    = tid & 3;                 // lane within 4-lane group
    const int item = block_item0 + li;
    const bool active = (li < ITEMS_PER_BLOCK) && (item < BN);

    int p0 = 0, p1 = 1, p2 = 2;
    get_perm(perm, p0, p1, p2);

    // ---- Per-item precompute (x4 redundant within group; cheap, fully overlapped with staging) ----
    float x0 = 0.f, x1 = 0.f, x2 = 1.f, y0 = 1.f, y1 = 0.f, y2 = 0.f;
    if (active) {
        const float* R = rot + (size_t)item * 9;
        x0 = R[0 * 3 + p0]; x1 = R[1 * 3 + p0]; x2 = R[2 * 3 + p0];
        y0 = R[0 * 3 + p1]; y1 = R[1 * 3 + p1]; y2 = R[2 * 3 + p1];
    }

    float xx = x0 * x0 + x1 * x1 + x2 * x2;
    float invxn = rsqrtf(xx);
    float r0 = -x0 * invxn, r1 = -x1 * invxn, r2 = -x2 * invxn;

    float v0 = y1 * r2 - y2 * r1;
    float v1 = y2 * r0 - y0 * r2;
    float v2 = y0 * r1 - y1 * r0;
    float invvn = rsqrtf(v0 * v0 + v1 * v1 + v2 * v2);
    v0 *= invvn; v1 *= invvn; v2 *= invvn;

    float yy = y0 * y0 + y1 * y1 + y2 * y2;
    float xy = x0 * y0 + x1 * y1 + x2 * y2;
    float xv = x0 * v0 + x1 * v1 + x2 * v2;
    float xr = x0 * r0 + x1 * r1 + x2 * r2;
    float yr = y0 * r0 + y1 * r1 + y2 * r2;
    float yv = y0 * v0 + y1 * v1 + y2 * v2;

    const float* Sbase = sm + li * SM_STRIDE;
    const float4* C4 = (const float4*)(cond + (size_t)block_item0 * 256);

    float accA = 0.0f, accD = 0.0f, accS = 0.0f;

    // ---- Two half-passes over k: halves the smem footprint -> 2x occupancy ----
    #pragma unroll
    for (int h = 0; h < 2; ++h) {
        if (h) __syncthreads();               // all reads of previous half done

        // Stage 63 items x 128 floats (32 float4 each): weights[32h..+32), w[32h..+32)
        #pragma unroll
        for (int it = 0; it < 8; ++it) {
            int g = it * 256 + tid;           // 0..2047 (need 2016)
            if (g < ITEMS_PER_BLOCK * 32) {
                int sli = g >> 5;             // staged item
                int t   = g & 31;             // float4 slot within item-half
                if (block_item0 + sli < BN) {
                    // src float4 idx within item: weights f4 8h+t (t<8), w f4 16+24h+(t-8)
                    int srcf4 = (t < 8) ? (8 * h + t) : (16 + 24 * h + t - 8);
                    float4 vdat = C4[sli * 64 + srcf4];
                    int dst = sli * SM_STRIDE + ((t < 8) ? 4 * t : 32 + 4 * (t - 8));
                    *(float4*)&sm[dst] = vdat;
                }
            }
        }
        __syncthreads();

        if (active) {
            #pragma unroll 4
            for (int j = 0; j < 8; ++j) {
                int kk = j * 4 + q;               // local k within half
                float wt  = Sbase[kk];
                float w0  = Sbase[32 + 3 * kk];
                float w1  = Sbase[33 + 3 * kk];
                float w2c = Sbase[34 + 3 * kk];

                float a  = y0 * w0 + y1 * w1 + y2 * w2c;
                float ww = w0 * w0 + w1 * w1 + w2c * w2c;
                float xw = x0 * w0 + x1 * w1 + x2 * w2c;
                float vw = v0 * w0 + v1 * w1 + v2 * w2c;
                float rw = r0 * w0 + r1 * w1 + r2 * w2c;

                float wpn2 = ww - a * a * (2.0f - yy);     // ||w - a*y||^2
                wpn2 = fmaxf(wpn2, 1e-30f);
                float iq  = rsqrtf(wpn2);
                float sq  = wpn2 * iq;                     // sqrt
                float s   = __fdividef(0.7f, 1.0f + sq);
                float w2n = s * s * wpn2;

                float sxw = s * (xw - a * xy);
                float svw = s * (vw - a * yv);
                float srw = s * (rw - a * yr);

                float n2 = xx - 2.0f * sxw + w2n;
                float factor = __fdividef(1.0f - w2n, n2);

                float hv = factor * (xv - svw) - svw;
                float hr = factor * (xr - srw) - srw;
                float ang = angle02pi(hv, hr);

                float sp = fmaxf(wt, 0.0f) + __logf(1.0f + __expf(-fabsf(wt)));

                accA = fmaf(sp, ang, accA);
                accD = fmaf(sp, factor, accD);   // ||dh_dtheta|| == factor (Householder)
                accS += sp;
            }
        }
    }

    if (active) {
        // ---- 4-lane butterfly reduction (quad-local mask; quads uniformly active) ----
        const unsigned qmask = 0xFu << (threadIdx.x & 28);
        #pragma unroll
        for (int off = 1; off < 4; off <<= 1) {
            accA += __shfl_xor_sync(qmask, accA, off);
            accD += __shfl_xor_sync(qmask, accD, off);
            accS += __shfl_xor_sync(qmask, accS, off);
        }

        float invS = __fdividef(1.0f, accS);
        float ang = accA * invS;
        float dtx = accD * invS;

        float sa, ca;
        __sincosf(ang, &sa, &ca);
        float t0 = r0 * ca + v0 * sa;
        float t1 = r1 * ca + v1 * sa;
        float t2 = r2 * ca + v2 * sa;

        int d = p1 - p0;
        float z0, z1, z2;
        if (d == 1 || d == -2) {           // tz = cross(tx, y)
            z0 = t1 * y2 - t2 * y1;
            z1 = t2 * y0 - t0 * y2;
            z2 = t0 * y1 - t1 * y0;
        } else {                           // tz = cross(y, tx)
            z0 = y1 * t2 - y2 * t1;
            z1 = y2 * t0 - y0 * t2;
            z2 = y0 * t1 - y1 * t0;
        }
        float invzn = rsqrtf(z0 * z0 + z1 * z1 + z2 * z2);
        z0 *= invzn; z1 *= invzn; z2 *= invzn;

        if (q == 0) sm[SM_LDJ + li] = __logf(dtx);

        #pragma unroll
        for (int idx = q; idx < 9; idx += 4) {
            int i = idx / 3, jj = idx % 3;
            float ti = (i == 0) ? t0 : ((i == 1) ? t1 : t2);
            float yi = (i == 0) ? y0 : ((i == 1) ? y1 : y2);
            float zi = (i == 0) ? z0 : ((i == 1) ? z1 : z2);
            float val = (jj == p0) ? ti : ((jj == p1) ? yi : zi);
            out_rot[(size_t)item * 9 + idx] = val;
        }
    }

    // ---- Fused deterministic ldj sum: block owns 3 whole b-groups of 21 ----
    __syncthreads();
    if (tid < 3) {
        int first_item = tid * 21;
        if (block_item0 + first_item < BN) {
            float sum = 0.0f;
            #pragma unroll
            for (int n = 0; n < 21; ++n)
                sum += sm[SM_LDJ + first_item + n];
            out_ldj[blockIdx.x * 3 + tid] = sum;
        }
    }
}

extern "C" void kernel_launch(void* const* d_in, const int* in_sizes, int n_in,
                              void* d_out, int out_size)
{
    const float* rot = (const float*)d_in[0];
    const float* cond = (const float*)d_in[1];
    const void* perm = d_in[2];
    float* out = (float*)d_out;

    int BN = in_sizes[0] / 9;            // 86016

    const int smem_bytes = (SM_LDJ + ITEMS_PER_BLOCK) * sizeof(float);   // ~33.5 KB
    cudaFuncSetAttribute(mobius_kernel, cudaFuncAttributeMaxDynamicSharedMemorySize, smem_bytes);

    int blocks = (BN + ITEMS_PER_BLOCK - 1) / ITEMS_PER_BLOCK;           // 1366
    mobius_kernel<<<blocks, 256, smem_bytes>>>(rot, cond, perm, out, out + in_sizes[0], BN);
}

// round 16
// speedup vs baseline: 1.0573x; 1.0525x over previous
#include <cuda_runtime.h>

#define ITEMS_PER_BLOCK 63     // 3 batch groups of 21 -> fused deterministic ldj sum
#define SM_STRIDE 132          // 128 floats per item-half + 4 pad (132 % 32 == 4 -> conflict-free)
#define SM_LDJ   (ITEMS_PER_BLOCK * SM_STRIDE)   // ldj scratch after cond area

// Robust permute parse: int32 view if it's a valid permutation of {0,1,2}, else int64.
__device__ __forceinline__ void get_perm(const void* pptr, int& p0, int& p1, int& p2)
{
    const int* pi = (const int*)pptr;
    int a = pi[0], b = pi[1], c = pi[2];
    bool ok = ((unsigned)a < 3u) && ((unsigned)b < 3u) && ((unsigned)c < 3u) &&
              (((1 << a) | (1 << b) | (1 << c)) == 7);
    if (!ok) {
        const long long* pl = (const long long*)pptr;
        a = (int)pl[0]; b = (int)pl[1]; c = (int)pl[2];
    }
    p0 = a; p1 = b; p2 = c;
}

// atan(t) for t >= 0, cephes-style two-stage range reduction, max err ~2e-7 rad.
__device__ __forceinline__ float atan_pos(float t)
{
    float y0, x;
    if (t > 2.414213562373095f)       { y0 = 1.5707963267948966f; x = __fdividef(-1.0f, t); }
    else if (t > 0.4142135623730950f) { y0 = 0.7853981633974483f; x = __fdividef(t - 1.0f, t + 1.0f); }
    else                              { y0 = 0.0f;                x = t; }
    float z = x * x;
    float p = ((8.05374449538e-2f * z - 1.38776856032e-1f) * z + 1.99777106478e-1f) * z
              - 3.33329491539e-1f;
    return y0 + fmaf(p * z, x, x);
}

// angle(hv, hr) in [0, 2*pi)
__device__ __forceinline__ float angle02pi(float hv, float hr)
{
    float ax = fabsf(hr), ay = fabsf(hv);
    float r = atan_pos(__fdividef(ay, ax));
    if (hr < 0.0f) r = 3.14159265358979323846f - r;
    if (hv < 0.0f) r = 6.28318530717958647692f - r;
    return r;
}

__global__ void __launch_bounds__(256, 5)
mobius_kernel(const float* __restrict__ rot,
              const float* __restrict__ cond,
              const void* __restrict__ perm,
              float* __restrict__ out_rot,
              float* __restrict__ out_ldj,   // out + BN*9
              int BN)
{
    extern __shared__ float sm[];
    const int tid = threadIdx.x;
    const int block_item0 = blockIdx.x * ITEMS_PER_BLOCK;

    const int li   = tid >> 2;                // local item 0..63 (63 inactive)
    const int q    = tid & 3;                 // lane within 4-lane group
    const int item = block_item0 + li;
    const bool active = (li < ITEMS_PER_BLOCK) && (item < BN);

    int p0 = 0, p1 = 1, p2 = 2;
    get_perm(perm, p0, p1, p2);

    // ---- Per-item precompute (x4 redundant within group; cheap, fully overlapped with staging) ----
    float x0 = 0.f, x1 = 0.f, x2 = 1.f, y0 = 1.f, y1 = 0.f, y2 = 0.f;
    if (active) {
        const float* R = rot + (size_t)item * 9;
        x0 = R[0 * 3 + p0]; x1 = R[1 * 3 + p0]; x2 = R[2 * 3 + p0];
        y0 = R[0 * 3 + p1]; y1 = R[1 * 3 + p1]; y2 = R[2 * 3 + p1];
    }

    float xx = x0 * x0 + x1 * x1 + x2 * x2;
    float invxn = rsqrtf(xx);
    float r0 = -x0 * invxn, r1 = -x1 * invxn, r2 = -x2 * invxn;

    float v0 = y1 * r2 - y2 * r1;
    float v1 = y2 * r0 - y0 * r2;
    float v2 = y0 * r1 - y1 * r0;
    float invvn = rsqrtf(v0 * v0 + v1 * v1 + v2 * v2);
    v0 *= invvn; v1 *= invvn; v2 *= invvn;

    float yy = y0 * y0 + y1 * y1 + y2 * y2;
    float xy = x0 * y0 + x1 * y1 + x2 * y2;
    float xv = x0 * v0 + x1 * v1 + x2 * v2;
    float xr = x0 * r0 + x1 * r1 + x2 * r2;
    float yr = y0 * r0 + y1 * r1 + y2 * r2;
    float yv = y0 * v0 + y1 * v1 + y2 * v2;

    const float* Sbase = sm + li * SM_STRIDE;
    const float4* C4 = (const float4*)(cond + (size_t)block_item0 * 256);

    float accA = 0.0f, accD = 0.0f, accS = 0.0f;

    // ---- Two half-passes over k: halves the smem footprint -> 2x occupancy ----
    #pragma unroll
    for (int h = 0; h < 2; ++h) {
        if (h) __syncthreads();               // all reads of previous half done

        // Stage 63 items x 128 floats (32 float4 each): weights[32h..+32), w[32h..+32)
        #pragma unroll
        for (int it = 0; it < 8; ++it) {
            int g = it * 256 + tid;           // 0..2047 (need 2016)
            if (g < ITEMS_PER_BLOCK * 32) {
                int sli = g >> 5;             // staged item
                int t   = g & 31;             // float4 slot within item-half
                if (block_item0 + sli < BN) {
                    // src float4 idx within item: weights f4 8h+t (t<8), w f4 16+24h+(t-8)
                    int srcf4 = (t < 8) ? (8 * h + t) : (16 + 24 * h + t - 8);
                    float4 vdat = C4[sli * 64 + srcf4];
                    int dst = sli * SM_STRIDE + ((t < 8) ? 4 * t : 32 + 4 * (t - 8));
                    *(float4*)&sm[dst] = vdat;
                }
            }
        }
        __syncthreads();

        if (active) {
            #pragma unroll 4
            for (int j = 0; j < 8; ++j) {
                int kk = j * 4 + q;               // local k within half
                float wt  = Sbase[kk];
                float w0  = Sbase[32 + 3 * kk];
                float w1  = Sbase[33 + 3 * kk];
                float w2c = Sbase[34 + 3 * kk];

                float a  = y0 * w0 + y1 * w1 + y2 * w2c;
                float ww = w0 * w0 + w1 * w1 + w2c * w2c;
                float xw = x0 * w0 + x1 * w1 + x2 * w2c;
                float vw = v0 * w0 + v1 * w1 + v2 * w2c;
                float rw = r0 * w0 + r1 * w1 + r2 * w2c;

                float wpn2 = ww - a * a * (2.0f - yy);     // ||w - a*y||^2
                wpn2 = fmaxf(wpn2, 1e-30f);
                float iq  = rsqrtf(wpn2);
                float sq  = wpn2 * iq;                     // sqrt
                float s   = __fdividef(0.7f, 1.0f + sq);
                float w2n = s * s * wpn2;

                float sxw = s * (xw - a * xy);
                float svw = s * (vw - a * yv);
                float srw = s * (rw - a * yr);

                float n2 = xx - 2.0f * sxw + w2n;
                float factor = __fdividef(1.0f - w2n, n2);

                float hv = factor * (xv - svw) - svw;
                float hr = factor * (xr - srw) - srw;
                float ang = angle02pi(hv, hr);

                float sp = fmaxf(wt, 0.0f) + __logf(1.0f + __expf(-fabsf(wt)));

                accA = fmaf(sp, ang, accA);
                accD = fmaf(sp, factor, accD);   // ||dh_dtheta|| == factor (Householder)
                accS += sp;
            }
        }
    }

    if (active) {
        // ---- 4-lane butterfly reduction (quad-local mask; quads uniformly active) ----
        const unsigned qmask = 0xFu << (threadIdx.x & 28);
        #pragma unroll
        for (int off = 1; off < 4; off <<= 1) {
            accA += __shfl_xor_sync(qmask, accA, off);
            accD += __shfl_xor_sync(qmask, accD, off);
            accS += __shfl_xor_sync(qmask, accS, off);
        }

        float invS = __fdividef(1.0f, accS);
        float ang = accA * invS;
        float dtx = accD * invS;

        float sa, ca;
        __sincosf(ang, &sa, &ca);
        float t0 = r0 * ca + v0 * sa;
        float t1 = r1 * ca + v1 * sa;
        float t2 = r2 * ca + v2 * sa;

        int d = p1 - p0;
        float z0, z1, z2;
        if (d == 1 || d == -2) {           // tz = cross(tx, y)
            z0 = t1 * y2 - t2 * y1;
            z1 = t2 * y0 - t0 * y2;
            z2 = t0 * y1 - t1 * y0;
        } else {                           // tz = cross(y, tx)
            z0 = y1 * t2 - y2 * t1;
            z1 = y2 * t0 - y0 * t2;
            z2 = y0 * t1 - y1 * t0;
        }
        float invzn = rsqrtf(z0 * z0 + z1 * z1 + z2 * z2);
        z0 *= invzn; z1 *= invzn; z2 *= invzn;

        if (q == 0) sm[SM_LDJ + li] = __logf(dtx);

        #pragma unroll
        for (int idx = q; idx < 9; idx += 4) {
            int i = idx / 3, jj = idx % 3;
            float ti = (i == 0) ? t0 : ((i == 1) ? t1 : t2);
            float yi = (i == 0) ? y0 : ((i == 1) ? y1 : y2);
            float zi = (i == 0) ? z0 : ((i == 1) ? z1 : z2);
            float val = (jj == p0) ? ti : ((jj == p1) ? yi : zi);
            out_rot[(size_t)item * 9 + idx] = val;
        }
    }

    // ---- Fused deterministic ldj sum: block owns 3 whole b-groups of 21 ----
    __syncthreads();
    if (tid < 3) {
        int first_item = tid * 21;
        if (block_item0 + first_item < BN) {
            float sum = 0.0f;
            #pragma unroll
            for (int n = 0; n < 21; ++n)
                sum += sm[SM_LDJ + first_item + n];
            out_ldj[blockIdx.x * 3 + tid] = sum;
        }
    }
}

extern "C" void kernel_launch(void* const* d_in, const int* in_sizes, int n_in,
                              void* d_out, int out_size)
{
    const float* rot = (const float*)d_in[0];
    const float* cond = (const float*)d_in[1];
    const void* perm = d_in[2];
    float* out = (float*)d_out;

    int BN = in_sizes[0] / 9;            // 86016

    const int smem_bytes = (SM_LDJ + ITEMS_PER_BLOCK) * sizeof(float);   // ~33.5 KB
    cudaFuncSetAttribute(mobius_kernel, cudaFuncAttributeMaxDynamicSharedMemorySize, smem_bytes);

    int blocks = (BN + ITEMS_PER_BLOCK - 1) / ITEMS_PER_BLOCK;           // 1366
    mobius_kernel<<<blocks, 256, smem_bytes>>>(rot, cond, perm, out, out + in_sizes[0], BN);
}